// round 9
// baseline (speedup 1.0000x reference)
#include <cuda_runtime.h>
#include <cuda_bf16.h>
#include <math.h>
#include <stdint.h>

// ---------------- problem constants ----------------
#define D_      2048
#define NTOK    8192
#define LAT     256
#define NEXP    32
#define EH      1024
#define SH      2048
#define ATOT    (NTOK*4)
#define ATOTP   (ATOT + NEXP*128)   // 36864
#define MAXTILES (ATOTP/128)        // 288
#define KCAT    (LAT + SH)          // 2304

#define BM 128
#define BK 64
#define STG 3          // non-dual stages
#define DSTG 3         // dual stages
#define BND 64         // dual per-set N tile

// ---------------- device scratch ----------------
__device__ __nv_bfloat16 g_hnorm_bf[NTOK*D_];
__device__ float g_rrms  [NTOK];
__device__ float g_scores[NTOK*NEXP];
__device__ __nv_bfloat16 g_latent_bf[NTOK*LAT];
__device__ __nv_bfloat16 g_ACTb[(size_t)ATOTP*EH];
__device__ float g_contrib[(size_t)ATOTP*LAT];
__device__ __nv_bfloat16 g_cat[(size_t)NTOK*KCAT];     // [eout | ACTS]
__device__ float g_gate  [NTOK];
__device__ float g_Psum  [NEXP];
__device__ int   g_count [NEXP];
__device__ int   g_off   [NEXP+1];
__device__ int   g_cursor[NEXP];
__device__ int   g_tile_e[MAXTILES];
__device__ int   g_tile_r[MAXTILES];
__device__ int   g_ntiles;
__device__ int   g_assign_tok[ATOTP];
__device__ int   g_assign_pos[ATOT];
__device__ int   g_topi[ATOT];
__device__ float g_topw[ATOT];

// bf16 weights
__device__ __nv_bfloat16 g_ldw_bf[(size_t)D_*LAT];
__device__ __nv_bfloat16 g_catW  [(size_t)KCAT*D_];    // [latent_up ; shared_w2]
__device__ __nv_bfloat16 g_Wcomb [(size_t)KCAT*D_];    // catW @ opw (bf16)
__device__ __nv_bfloat16 g_ew1_bf[(size_t)NEXP*LAT*2*EH];
__device__ __nv_bfloat16 g_ew2_bf[(size_t)NEXP*EH*LAT];
__device__ __nv_bfloat16 g_sw1_bf[(size_t)D_*2*SH];
__device__ __nv_bfloat16 g_opw_bf[(size_t)D_*D_];

// ---------------- asm helpers ----------------
__device__ __forceinline__ uint32_t s2u(const void* p) {
    uint32_t a;
    asm("{ .reg .u64 t; cvta.to.shared.u64 t, %1; cvt.u32.u64 %0, t; }" : "=r"(a) : "l"(p));
    return a;
}
__device__ __forceinline__ void cp16(uint32_t d, const void* s) {
    asm volatile("cp.async.cg.shared.global [%0], [%1], 16;" :: "r"(d), "l"(s));
}
__device__ __forceinline__ void ldmx4(uint32_t* r, uint32_t a) {
    asm volatile("ldmatrix.sync.aligned.m8n8.x4.shared.b16 {%0,%1,%2,%3}, [%4];"
        : "=r"(r[0]), "=r"(r[1]), "=r"(r[2]), "=r"(r[3]) : "r"(a));
}
__device__ __forceinline__ void ldmx4t(uint32_t* r, uint32_t a) {
    asm volatile("ldmatrix.sync.aligned.m8n8.x4.trans.shared.b16 {%0,%1,%2,%3}, [%4];"
        : "=r"(r[0]), "=r"(r[1]), "=r"(r[2]), "=r"(r[3]) : "r"(a));
}
__device__ __forceinline__ void mma16816(float* c, const uint32_t* a, const uint32_t* b) {
    asm volatile("mma.sync.aligned.m16n8k16.row.col.f32.bf16.bf16.f32 "
        "{%0,%1,%2,%3},{%4,%5,%6,%7},{%8,%9},{%0,%1,%2,%3};"
        : "+f"(c[0]), "+f"(c[1]), "+f"(c[2]), "+f"(c[3])
        : "r"(a[0]), "r"(a[1]), "r"(a[2]), "r"(a[3]), "r"(b[0]), "r"(b[1]));
}

// ---------------- rmsnorm: bf16 hnorm + rrms + fused shared gate ----------------
__global__ void k_rmsnorm(const float* __restrict__ h, const float* __restrict__ w,
                          const float* __restrict__ gw)
{
    int n = blockIdx.x;
    const float4* hp = (const float4*)(h + (size_t)n * D_);
    const float4* wp = (const float4*)w;
    const float4* gp = (const float4*)gw;
    float ss = 0.f, gg = 0.f;
    for (int i = threadIdx.x; i < D_/4; i += 256) {
        float4 v = hp[i], wv = wp[i], gv = gp[i];
        ss += v.x*v.x + v.y*v.y + v.z*v.z + v.w*v.w;
        gg += v.x*wv.x*gv.x + v.y*wv.y*gv.y + v.z*wv.z*gv.z + v.w*wv.w*gv.w;
    }
    __shared__ float red[256], red2[256];
    red[threadIdx.x] = ss; red2[threadIdx.x] = gg; __syncthreads();
    for (int s = 128; s; s >>= 1) {
        if (threadIdx.x < s) { red[threadIdx.x] += red[threadIdx.x + s];
                               red2[threadIdx.x] += red2[threadIdx.x + s]; }
        __syncthreads();
    }
    float rs = rsqrtf(red[0] * (1.f / D_) + 1e-6f);
    if (threadIdx.x == 0) {
        g_gate[n] = 1.f / (1.f + expf(-rs * red2[0]));
        g_rrms[n] = rs;
    }
    __nv_bfloat162* bp = (__nv_bfloat162*)(g_hnorm_bf + (size_t)n * D_);
    for (int i = threadIdx.x; i < D_/4; i += 256) {
        float4 v = hp[i], wv = wp[i];
        v.x *= rs*wv.x; v.y *= rs*wv.y; v.z *= rs*wv.z; v.w *= rs*wv.w;
        bp[i*2+0] = __floats2bfloat162_rn(v.x, v.y);
        bp[i*2+1] = __floats2bfloat162_rn(v.z, v.w);
    }
}

// ---------------- router: recomputes hnorm = h*(rrms*w) in fp32 (bit-identical) ----------------
__global__ void k_router(const float* __restrict__ h, const float* __restrict__ rw,
                         const float* __restrict__ rb, const float* __restrict__ nw)
{
    __shared__ float hs[32][64];
    __shared__ float ws[64][32];
    __shared__ float s_r[32];
    int n0 = blockIdx.x * 32;
    int tid = threadIdx.x;
    int e = tid & 31, tr = tid >> 5;
    if (tid < 32) s_r[tid] = g_rrms[n0 + tid];
    __syncthreads();
    float acc[4] = {0.f,0.f,0.f,0.f};
    for (int k0 = 0; k0 < D_; k0 += 64) {
        #pragma unroll
        for (int i = 0; i < 8; i++) {
            int lin = tid + i*256;
            int t = lin >> 6, k = lin & 63;
            hs[t][k] = h[(size_t)(n0 + t)*D_ + k0 + k] * (s_r[t] * nw[k0 + k]);
            int kw = lin >> 5, ew = lin & 31;
            ws[kw][ew] = rw[(size_t)(k0 + kw)*NEXP + ew];
        }
        __syncthreads();
        #pragma unroll
        for (int kk = 0; kk < 64; kk++)
            #pragma unroll
            for (int i = 0; i < 4; i++)
                acc[i] += hs[tr + 8*i][kk] * ws[kk][e];
        __syncthreads();
    }
    float bias = rb[e];
    #pragma unroll
    for (int i = 0; i < 4; i++) {
        float v = acc[i] + bias;
        g_scores[(n0 + tr + 8*i)*NEXP + e] = 1.f / (1.f + expf(-v));
    }
}

__global__ void k_topk()
{
    int warp = threadIdx.x >> 5, lane = threadIdx.x & 31;
    int n = blockIdx.x * 8 + warp;
    float s = g_scores[n*NEXP + lane];
    float topv[4]; int topi[4];
    #pragma unroll
    for (int k = 0; k < 4; k++) {
        float v = s; int bi = lane;
        #pragma unroll
        for (int off = 16; off; off >>= 1) {
            float v2 = __shfl_xor_sync(0xffffffffu, v, off);
            int   i2 = __shfl_xor_sync(0xffffffffu, bi, off);
            if (v2 > v || (v2 == v && i2 < bi)) { v = v2; bi = i2; }
        }
        topv[k] = v; topi[k] = bi;
        if (lane == bi) s = -1e30f;
    }
    if (lane == 0) {
        float inv = 1.f / (topv[0]+topv[1]+topv[2]+topv[3] + 1e-8f);
        #pragma unroll
        for (int k = 0; k < 4; k++) {
            g_topw[n*4 + k] = topv[k] * inv;
            g_topi[n*4 + k] = topi[k];
            atomicAdd(&g_count[topi[k]], 1);
        }
    }
}

__global__ void k_colsum()
{
    int e = blockIdx.x;
    float s = 0.f;
    for (int n = threadIdx.x; n < NTOK; n += 256) s += g_scores[n*NEXP + e];
    __shared__ float red[256];
    red[threadIdx.x] = s; __syncthreads();
    for (int st = 128; st; st >>= 1) {
        if (threadIdx.x < st) red[threadIdx.x] += red[threadIdx.x + st];
        __syncthreads();
    }
    if (threadIdx.x == 0) g_Psum[e] = red[0];
}

__global__ void k_offsets()
{
    if (threadIdx.x == 0) {
        int acc = 0, nt = 0;
        for (int e = 0; e < NEXP; e++) {
            g_off[e] = acc; g_cursor[e] = acc;
            int nep = (g_count[e] + 127) & ~127;
            for (int r = 0; r < nep; r += 128) {
                g_tile_e[nt] = e; g_tile_r[nt] = acc + r; nt++;
            }
            acc += nep;
        }
        g_off[NEXP] = acc;
        g_ntiles = nt;
    }
}

__global__ void k_assign()
{
    int n = blockIdx.x * 256 + threadIdx.x;
    if (n >= NTOK) return;
    #pragma unroll
    for (int k = 0; k < 4; k++) {
        int e = g_topi[n*4 + k];
        int pos = atomicAdd(&g_cursor[e], 1);
        g_assign_tok[pos] = n;
        g_assign_pos[n*4 + k] = pos;
    }
}

__global__ void k_combine()
{
    int n = blockIdx.x, c = threadIdx.x;   // 256 threads == LAT
    float acc = 0.f;
    #pragma unroll
    for (int k = 0; k < 4; k++) {
        int pos = g_assign_pos[n*4 + k];
        acc += g_topw[n*4 + k] * g_contrib[(size_t)pos * LAT + c];
    }
    g_cat[(size_t)n * KCAT + c] = __float2bfloat16(acc);
}

__global__ void k_lb(float* out, int out_size)
{
    if (threadIdx.x == 0 && out_size > NTOK * D_) {
        float s = 0.f;
        for (int e = 0; e < NEXP; e++)
            s += ((float)g_count[e] / NTOK) * (g_Psum[e] / NTOK);
        out[NTOK * D_] = (float)NEXP * s * 1e-4f;
    }
}

__global__ void k_cvt(const float* __restrict__ a, __nv_bfloat16* __restrict__ b, long n)
{
    long i = ((long)blockIdx.x*256 + threadIdx.x) * 16;
    if (i >= n) return;
    float4 v0 = *(const float4*)(a + i);
    float4 v1 = *(const float4*)(a + i + 4);
    float4 v2 = *(const float4*)(a + i + 8);
    float4 v3 = *(const float4*)(a + i + 12);
    __nv_bfloat162 o[8];
    o[0] = __floats2bfloat162_rn(v0.x, v0.y);
    o[1] = __floats2bfloat162_rn(v0.z, v0.w);
    o[2] = __floats2bfloat162_rn(v1.x, v1.y);
    o[3] = __floats2bfloat162_rn(v1.z, v1.w);
    o[4] = __floats2bfloat162_rn(v2.x, v2.y);
    o[5] = __floats2bfloat162_rn(v2.z, v2.w);
    o[6] = __floats2bfloat162_rn(v3.x, v3.y);
    o[7] = __floats2bfloat162_rn(v3.z, v3.w);
    *(uint4*)(b + i)     = *(uint4*)&o[0];
    *(uint4*)(b + i + 8) = *(uint4*)&o[4];
}

// ====== DUAL mma GEMM (gate+lin, fused spike): 128 thr, 2x2 warps, 64x32 dual,
//        BN=64 per set, BK=64, 3-stage. 2 CTAs/SM. ======
template<bool GROUPED, bool GATHER, bool GATED>
__global__ void __launch_bounds__(128)
k_mmdual(const __nv_bfloat16* __restrict__ A, int lda,
         const __nv_bfloat16* __restrict__ Bt, long bstride, int ldb,
         __nv_bfloat16* __restrict__ Cout, int ldc,
         const float* __restrict__ vth, int HID, int K)
{
    extern __shared__ __align__(16) char smem[];
    __shared__ int s_tok[BM];

    const int tid = threadIdx.x;
    const int lane = tid & 31;
    const int wid = tid >> 5;
    const int wm = wid >> 1, wn = wid & 1;

    int e = 0, r0, n0;
    if (GROUPED) {
        int bt = blockIdx.x;
        if (bt >= g_ntiles) return;
        e = g_tile_e[bt]; r0 = g_tile_r[bt]; n0 = blockIdx.y * BND;
    } else {
        r0 = blockIdx.y * BM; n0 = blockIdx.x * BND;
    }
    const __nv_bfloat16* B = Bt + (GROUPED ? (size_t)e * bstride : 0);

    const uint32_t sb = s2u(smem);
    const uint32_t LDA_B = (BK + 8) * 2;    // 144
    const uint32_t LDB_B = (BND + 8) * 2;   // 144
    const uint32_t A_ST = BM * LDA_B;       // 18432
    const uint32_t B_ST = BK * LDB_B;       // 9216
    const uint32_t bOff  = DSTG * A_ST;
    const uint32_t b2Off = DSTG * (A_ST + B_ST);

    if (GATHER) {
        s_tok[tid] = g_assign_tok[r0 + tid];
        __syncthreads();
    }

    const int nk = K / BK;

    auto issue = [&](int kt) {
        int st = kt % DSTG;
        uint32_t sa  = sb + st * A_ST;
        uint32_t sbb = sb + bOff + st * B_ST;
        uint32_t sb2 = sb + b2Off + st * B_ST;
        #pragma unroll
        for (int i = 0; i < 8; i++) {
            int lin = i*128 + tid;
            int row = lin >> 3, c8 = (lin & 7) * 8;
            const __nv_bfloat16* src = GATHER
                ? A + (size_t)s_tok[row]*lda + kt*BK + c8
                : A + (size_t)(r0 + row)*lda + kt*BK + c8;
            cp16(sa + row*LDA_B + c8*2, src);
        }
        #pragma unroll
        for (int i = 0; i < 4; i++) {
            int lin = i*128 + tid;
            int row = lin >> 3, c8 = (lin & 7) * 8;
            cp16(sbb + row*LDB_B + c8*2, B + (size_t)(kt*BK + row)*ldb + n0 + c8);
            cp16(sb2 + row*LDB_B + c8*2, B + (size_t)(kt*BK + row)*ldb + (n0 + HID) + c8);
        }
        asm volatile("cp.async.commit_group;" ::: "memory");
    };

    float acc [4][4][4], acc2[4][4][4];
    #pragma unroll
    for (int i = 0; i < 4; i++)
        #pragma unroll
        for (int j = 0; j < 4; j++)
            #pragma unroll
            for (int t = 0; t < 4; t++) { acc[i][j][t] = 0.f; acc2[i][j][t] = 0.f; }

    issue(0);
    if (nk > 1) issue(1);

    for (int kt = 0; kt < nk; kt++) {
        if (kt + 2 < nk) asm volatile("cp.async.wait_group 1;" ::: "memory");
        else             asm volatile("cp.async.wait_group 0;" ::: "memory");
        __syncthreads();
        if (kt + 2 < nk) issue(kt + 2);

        int st = kt % DSTG;
        uint32_t sa  = sb + st * A_ST;
        uint32_t sbb = sb + bOff + st * B_ST;
        uint32_t sb2 = sb + b2Off + st * B_ST;

        #pragma unroll
        for (int k16 = 0; k16 < BK/16; k16++) {
            uint32_t a[4][4];
            #pragma unroll
            for (int mi = 0; mi < 4; mi++) {
                uint32_t addr = sa + (wm*64 + mi*16 + (lane & 15))*LDA_B
                                   + (k16*16 + (lane >> 4)*8)*2;
                ldmx4(a[mi], addr);
            }
            uint32_t b[4][2], b2[4][2];
            #pragma unroll
            for (int nj = 0; nj < 2; nj++) {
                uint32_t addr = sbb + (k16*16 + (lane & 15))*LDB_B
                                    + (wn*32 + nj*16 + (lane >> 4)*8)*2;
                uint32_t r[4]; ldmx4t(r, addr);
                b[nj*2][0] = r[0]; b[nj*2][1] = r[1];
                b[nj*2+1][0] = r[2]; b[nj*2+1][1] = r[3];
                uint32_t addr2 = sb2 + (k16*16 + (lane & 15))*LDB_B
                                     + (wn*32 + nj*16 + (lane >> 4)*8)*2;
                uint32_t r2[4]; ldmx4t(r2, addr2);
                b2[nj*2][0] = r2[0]; b2[nj*2][1] = r2[1];
                b2[nj*2+1][0] = r2[2]; b2[nj*2+1][1] = r2[3];
            }
            #pragma unroll
            for (int mi = 0; mi < 4; mi++)
                #pragma unroll
                for (int n8 = 0; n8 < 4; n8++) {
                    mma16816(acc[mi][n8], a[mi], b[n8]);
                    mma16816(acc2[mi][n8], a[mi], b2[n8]);
                }
        }
    }

    const int rbase = r0 + wm*64;
    const int cbase = wn*32;
    const float* vthE = vth + (GROUPED ? (size_t)e * HID : 0);
    #pragma unroll
    for (int mi = 0; mi < 4; mi++) {
        int r = rbase + mi*16 + (lane >> 2);
        float gs0 = GATED ? g_gate[r]     : 1.f;
        float gs1 = GATED ? g_gate[r + 8] : 1.f;
        #pragma unroll
        for (int n8 = 0; n8 < 4; n8++) {
            int c = n0 + cbase + n8*8 + (lane & 3)*2;
            float v0 = vthE[c], v1 = vthE[c + 1];
            float o0 = (acc[mi][n8][0] >= v0 ? v0 : 0.f) * acc2[mi][n8][0] * gs0;
            float o1 = (acc[mi][n8][1] >= v1 ? v1 : 0.f) * acc2[mi][n8][1] * gs0;
            float o2 = (acc[mi][n8][2] >= v0 ? v0 : 0.f) * acc2[mi][n8][2] * gs1;
            float o3 = (acc[mi][n8][3] >= v1 ? v1 : 0.f) * acc2[mi][n8][3] * gs1;
            *(__nv_bfloat162*)(Cout + (size_t)r*ldc + c)     = __floats2bfloat162_rn(o0, o1);
            *(__nv_bfloat162*)(Cout + (size_t)(r+8)*ldc + c) = __floats2bfloat162_rn(o2, o3);
        }
    }
}

// ====== non-dual mma GEMM: 128 thr, 2x2 warps, warp 64x(NT/2), BK=64, 3-stage ======
template<int NT, bool GROUPED, bool RESID, bool OUTBF>
__global__ void __launch_bounds__(128)
k_mm64(const __nv_bfloat16* __restrict__ A, int lda,
       const __nv_bfloat16* __restrict__ Bt, long bstride, int ldb,
       void* __restrict__ Cout, int ldc,
       const float* __restrict__ resid, int ldr, int K)
{
    extern __shared__ __align__(16) char smem[];

    const int tid = threadIdx.x;
    const int lane = tid & 31;
    const int wid = tid >> 5;
    const int wm = wid >> 1, wn = wid & 1;
    constexpr int N8 = NT / 16;        // n8 blocks per warp
    constexpr int NJ = NT / 32;        // ldmx4t per warp per k16
    constexpr int NLD = NT / 16;       // B cp16 iterations

    int e = 0, r0, n0;
    if (GROUPED) {
        int bt = blockIdx.x;
        if (bt >= g_ntiles) return;
        e = g_tile_e[bt]; r0 = g_tile_r[bt]; n0 = blockIdx.y * NT;
    } else {
        r0 = blockIdx.y * BM; n0 = blockIdx.x * NT;
    }
    const __nv_bfloat16* B = Bt + (GROUPED ? (size_t)e * bstride : 0);

    const uint32_t sb = s2u(smem);
    const uint32_t LDA_B = (BK + 8) * 2;
    const uint32_t LDB_B = (NT + 8) * 2;
    const uint32_t A_ST = BM * LDA_B;
    const uint32_t B_ST = BK * LDB_B;
    const uint32_t bOff = STG * A_ST;

    const int nk = K / BK;

    auto issue = [&](int kt) {
        int st = kt % STG;
        uint32_t sa  = sb + st * A_ST;
        uint32_t sbb = sb + bOff + st * B_ST;
        #pragma unroll
        for (int i = 0; i < 8; i++) {
            int lin = i*128 + tid;
            int row = lin >> 3, c8 = (lin & 7) * 8;
            cp16(sa + row*LDA_B + c8*2, A + (size_t)(r0 + row)*lda + kt*BK + c8);
        }
        #pragma unroll
        for (int i = 0; i < NLD; i++) {
            int lin = i*128 + tid;
            int row = lin / (NT/8), c8 = (lin % (NT/8)) * 8;
            cp16(sbb + row*LDB_B + c8*2, B + (size_t)(kt*BK + row)*ldb + n0 + c8);
        }
        asm volatile("cp.async.commit_group;" ::: "memory");
    };

    float acc[4][N8][4];
    #pragma unroll
    for (int i = 0; i < 4; i++)
        #pragma unroll
        for (int j = 0; j < N8; j++)
            #pragma unroll
            for (int t = 0; t < 4; t++) acc[i][j][t] = 0.f;

    issue(0);
    if (nk > 1) issue(1);

    for (int kt = 0; kt < nk; kt++) {
        if (kt + 2 < nk) asm volatile("cp.async.wait_group 1;" ::: "memory");
        else             asm volatile("cp.async.wait_group 0;" ::: "memory");
        __syncthreads();
        if (kt + 2 < nk) issue(kt + 2);

        int st = kt % STG;
        uint32_t sa  = sb + st * A_ST;
        uint32_t sbb = sb + bOff + st * B_ST;

        #pragma unroll
        for (int k16 = 0; k16 < BK/16; k16++) {
            uint32_t a[4][4];
            #pragma unroll
            for (int mi = 0; mi < 4; mi++) {
                uint32_t addr = sa + (wm*64 + mi*16 + (lane & 15))*LDA_B
                                   + (k16*16 + (lane >> 4)*8)*2;
                ldmx4(a[mi], addr);
            }
            uint32_t b[N8][2];
            #pragma unroll
            for (int nj = 0; nj < NJ; nj++) {
                uint32_t addr = sbb + (k16*16 + (lane & 15))*LDB_B
                                    + (wn*(NT/2) + nj*16 + (lane >> 4)*8)*2;
                uint32_t r[4]; ldmx4t(r, addr);
                b[nj*2][0] = r[0]; b[nj*2][1] = r[1];
                b[nj*2+1][0] = r[2]; b[nj*2+1][1] = r[3];
            }
            #pragma unroll
            for (int mi = 0; mi < 4; mi++)
                #pragma unroll
                for (int n8 = 0; n8 < N8; n8++)
                    mma16816(acc[mi][n8], a[mi], b[n8]);
        }
    }

    const int rbase = r0 + wm*64;
    const int cbase = wn*(NT/2);
    #pragma unroll
    for (int mi = 0; mi < 4; mi++) {
        int r = rbase + mi*16 + (lane >> 2);
        #pragma unroll
        for (int n8 = 0; n8 < N8; n8++) {
            int c = n0 + cbase + n8*8 + (lane & 3)*2;
            float o0 = acc[mi][n8][0], o1 = acc[mi][n8][1];
            float o2 = acc[mi][n8][2], o3 = acc[mi][n8][3];
            if (RESID) {
                float2 r0v = *(const float2*)(resid + (size_t)r*ldr + c);
                float2 r1v = *(const float2*)(resid + (size_t)(r+8)*ldr + c);
                o0 += r0v.x; o1 += r0v.y; o2 += r1v.x; o3 += r1v.y;
            }
            if (OUTBF) {
                __nv_bfloat16* op = (__nv_bfloat16*)Cout;
                *(__nv_bfloat162*)(op + (size_t)r*ldc + c)     = __floats2bfloat162_rn(o0, o1);
                *(__nv_bfloat162*)(op + (size_t)(r+8)*ldc + c) = __floats2bfloat162_rn(o2, o3);
            } else {
                float* op = (float*)Cout;
                *(float2*)(op + (size_t)r*ldc + c)     = make_float2(o0, o1);
                *(float2*)(op + (size_t)(r+8)*ldc + c) = make_float2(o2, o3);
            }
        }
    }
}

// ---------------- launch ----------------
static inline int cvtGrid(long n) { return (int)((n/16 + 255) / 256); }

extern "C" void kernel_launch(void* const* d_in, const int* in_sizes, int n_in,
                              void* d_out, int out_size)
{
    const float* h         = (const float*)d_in[0];
    const float* norm_w    = (const float*)d_in[1];
    const float* latent_dw = (const float*)d_in[2];
    const float* latent_uw = (const float*)d_in[3];
    const float* router_w  = (const float*)d_in[4];
    const float* router_b  = (const float*)d_in[5];
    const float* ew1       = (const float*)d_in[6];
    const float* evth      = (const float*)d_in[7];
    const float* ew2       = (const float*)d_in[8];
    const float* sw1       = (const float*)d_in[9];
    const float* svth      = (const float*)d_in[10];
    const float* sw2       = (const float*)d_in[11];
    const float* sgw       = (const float*)d_in[12];
    const float* opw       = (const float*)d_in[13];
    float* out = (float*)d_out;

    auto MMe1 = k_mmdual<true , true , false>;       // exp1 fused spike -> ACTb
    auto MMs1 = k_mmdual<false, false, true >;       // shared_w1 fused spike*gate -> g_cat[:,256:]
    auto MMld = k_mm64<64 , false, false, true >;    // latent_down -> latent bf16
    auto MMe2 = k_mm64<64 , true , false, false>;    // exp2 -> contrib fp32
    auto MMwc = k_mm64<128, false, false, true >;    // W_comb = catW @ opw -> bf16
    auto MMfin= k_mm64<128, false, true , false>;    // out = h + cat @ W_comb (fp32)

    const uint32_t A_ST   = BM*(BK+8)*2;             // 18432
    const uint32_t B_ST128= BK*(128+8)*2;            // 17408
    const uint32_t B_ST64 = BK*(64+8)*2;             // 9216
    const int SM128 = STG*(A_ST + B_ST128);          // 107520
    const int SM64  = STG*(A_ST + B_ST64);           // 82944
    const int SMD   = DSTG*(A_ST + 2*B_ST64);        // 110592
    cudaFuncSetAttribute(MMe1, cudaFuncAttributeMaxDynamicSharedMemorySize, SMD);
    cudaFuncSetAttribute(MMs1, cudaFuncAttributeMaxDynamicSharedMemorySize, SMD);
    cudaFuncSetAttribute(MMld, cudaFuncAttributeMaxDynamicSharedMemorySize, SM64);
    cudaFuncSetAttribute(MMe2, cudaFuncAttributeMaxDynamicSharedMemorySize, SM64);
    cudaFuncSetAttribute(MMwc, cudaFuncAttributeMaxDynamicSharedMemorySize, SM128);
    cudaFuncSetAttribute(MMfin,cudaFuncAttributeMaxDynamicSharedMemorySize, SM128);

    void *p_count, *p_atok, *p_hbf, *p_lbf, *p_ACTb, *p_contrib, *p_cat;
    void *p_ldw, *p_catW, *p_Wcomb, *p_ew1, *p_ew2, *p_sw1, *p_opw;
    cudaGetSymbolAddress(&p_count, g_count);
    cudaGetSymbolAddress(&p_atok,  g_assign_tok);
    cudaGetSymbolAddress(&p_hbf,   g_hnorm_bf);
    cudaGetSymbolAddress(&p_lbf,   g_latent_bf);
    cudaGetSymbolAddress(&p_ACTb,  g_ACTb);
    cudaGetSymbolAddress(&p_contrib, g_contrib);
    cudaGetSymbolAddress(&p_cat,   g_cat);
    cudaGetSymbolAddress(&p_ldw,   g_ldw_bf);
    cudaGetSymbolAddress(&p_catW,  g_catW);
    cudaGetSymbolAddress(&p_Wcomb, g_Wcomb);
    cudaGetSymbolAddress(&p_ew1,   g_ew1_bf);
    cudaGetSymbolAddress(&p_ew2,   g_ew2_bf);
    cudaGetSymbolAddress(&p_sw1,   g_sw1_bf);
    cudaGetSymbolAddress(&p_opw,   g_opw_bf);

    // --- launches 1-5 ---
    k_rmsnorm<<<NTOK, 256>>>(h, norm_w, sgw);
    k_cvt<<<cvtGrid((long)D_*2*SH), 256>>>(sw1, (__nv_bfloat16*)p_sw1, (long)D_*2*SH);
    k_cvt<<<cvtGrid((long)D_*LAT), 256>>>(latent_dw, (__nv_bfloat16*)p_ldw, (long)D_*LAT);
    k_cvt<<<cvtGrid((long)LAT*D_), 256>>>(latent_uw, (__nv_bfloat16*)p_catW, (long)LAT*D_);
    k_cvt<<<cvtGrid((long)NEXP*LAT*2*EH), 256>>>(ew1, (__nv_bfloat16*)p_ew1, (long)NEXP*LAT*2*EH);

    // --- launch 6: big DUAL shared_w1 GEMM ---
    MMs1<<<dim3(SH/BND, NTOK/128), 128, SMD>>>((const __nv_bfloat16*)p_hbf, D_,
        (const __nv_bfloat16*)p_sw1, 0, 2*SH,
        (__nv_bfloat16*)p_cat + LAT, KCAT, svth, SH, D_);

    // --- remaining conversions ---
    k_cvt<<<cvtGrid((long)NEXP*EH*LAT), 256>>>(ew2, (__nv_bfloat16*)p_ew2, (long)NEXP*EH*LAT);
    k_cvt<<<cvtGrid((long)SH*D_), 256>>>(sw2, (__nv_bfloat16*)p_catW + (size_t)LAT*D_, (long)SH*D_);
    k_cvt<<<cvtGrid((long)D_*D_), 256>>>(opw, (__nv_bfloat16*)p_opw, (long)D_*D_);

    // W_comb = [latent_up; shared_w2] @ opw   (2304 x 2048, K=2048) -> bf16
    MMwc<<<dim3(D_/128, KCAT/128), 128, SM128>>>((const __nv_bfloat16*)p_catW, D_,
        (const __nv_bfloat16*)p_opw, 0, D_, p_Wcomb, D_, nullptr, 0, D_);

    cudaMemsetAsync(p_count, 0, NEXP * sizeof(int));
    cudaMemsetAsync(p_atok,  0, ATOTP * sizeof(int));

    k_router <<<NTOK/32, 256>>>(h, router_w, router_b, norm_w);
    k_topk   <<<NTOK/8, 256>>>();
    k_colsum <<<NEXP, 256>>>();
    k_offsets<<<1, 32>>>();
    k_assign <<<NTOK/256, 256>>>();

    // latent = hnorm @ latent_down  -> bf16   (BN=64: grid 4x64)
    MMld<<<dim3(LAT/64, NTOK/128), 128, SM64>>>((const __nv_bfloat16*)p_hbf, D_,
        (const __nv_bfloat16*)p_ldw, 0, LAT, p_lbf, LAT, nullptr, 0, D_);

    // exp1 fused spike -> ACTb bf16
    MMe1<<<dim3(MAXTILES, EH/BND), 128, SMD>>>((const __nv_bfloat16*)p_lbf, LAT,
        (const __nv_bfloat16*)p_ew1, (long)LAT*2*EH, 2*EH,
        (__nv_bfloat16*)p_ACTb, EH, evth, EH, LAT);

    // exp2 -> contrib fp32   (BN=64: grid 288x4)
    MMe2<<<dim3(MAXTILES, LAT/64), 128, SM64>>>((const __nv_bfloat16*)p_ACTb, EH,
        (const __nv_bfloat16*)p_ew2, (long)EH*LAT, LAT, p_contrib, LAT, nullptr, 0, EH);

    k_combine<<<NTOK, LAT>>>();

    // out = h + [eout|ACTS] @ W_comb   (K=2304, fp32 out)
    MMfin<<<dim3(D_/128, NTOK/128), 128, SM128>>>((const __nv_bfloat16*)p_cat, KCAT,
        (const __nv_bfloat16*)p_Wcomb, 0, D_, out, D_, h, D_, KCAT);

    k_lb<<<1, 32>>>(out, out_size);
}

// round 14
// speedup vs baseline: 1.0686x; 1.0686x over previous
#include <cuda_runtime.h>
#include <cuda_bf16.h>
#include <math.h>
#include <stdint.h>

// ---------------- problem constants ----------------
#define D_      2048
#define NTOK    8192
#define LAT     256
#define NEXP    32
#define EH      1024
#define SH      2048
#define ATOT    (NTOK*4)
#define ATOTP   (ATOT + NEXP*128)   // 36864
#define MAXTILES (ATOTP/128)        // 288
#define KCAT    (LAT + SH)          // 2304

#define BM 128
#define BN 128
#define BK 64
#define STG 3          // non-dual stages
#define DSTG 2         // dual stages
#define BND 64         // dual per-set N tile

// ---------------- device scratch ----------------
__device__ __nv_bfloat16 g_hnorm_bf[NTOK*D_];
__device__ float g_rrms  [NTOK];
__device__ float g_scores[NTOK*NEXP];
__device__ __nv_bfloat16 g_latent_bf[NTOK*LAT];
__device__ __nv_bfloat16 g_ACTb[(size_t)ATOTP*EH];
__device__ __nv_bfloat16 g_contrib_bf[(size_t)ATOTP*LAT];
__device__ __nv_bfloat16 g_cat[(size_t)NTOK*KCAT];     // [eout | ACTS]
__device__ float g_gate  [NTOK];
__device__ float g_Psum  [NEXP];
__device__ int   g_count [NEXP];
__device__ int   g_off   [NEXP+1];
__device__ int   g_cursor[NEXP];
__device__ int   g_tile_e[MAXTILES];
__device__ int   g_tile_r[MAXTILES];
__device__ int   g_ntiles;
__device__ int   g_assign_tok[ATOTP];
__device__ int   g_assign_pos[ATOT];
__device__ int   g_topi[ATOT];
__device__ float g_topw[ATOT];

// bf16 weights
__device__ __nv_bfloat16 g_ldw_bf[(size_t)D_*LAT];
__device__ __nv_bfloat16 g_catW  [(size_t)KCAT*D_];    // [latent_up ; shared_w2]
__device__ __nv_bfloat16 g_Wcomb [(size_t)KCAT*D_];    // catW @ opw (bf16)
__device__ __nv_bfloat16 g_ew1_bf[(size_t)NEXP*LAT*2*EH];
__device__ __nv_bfloat16 g_ew2_bf[(size_t)NEXP*EH*LAT];
__device__ __nv_bfloat16 g_sw1_bf[(size_t)D_*2*SH];
__device__ __nv_bfloat16 g_opw_bf[(size_t)D_*D_];

// ---------------- asm helpers ----------------
__device__ __forceinline__ uint32_t s2u(const void* p) {
    uint32_t a;
    asm("{ .reg .u64 t; cvta.to.shared.u64 t, %1; cvt.u32.u64 %0, t; }" : "=r"(a) : "l"(p));
    return a;
}
__device__ __forceinline__ void cp16(uint32_t d, const void* s) {
    asm volatile("cp.async.cg.shared.global [%0], [%1], 16;" :: "r"(d), "l"(s));
}
__device__ __forceinline__ void ldmx4(uint32_t* r, uint32_t a) {
    asm volatile("ldmatrix.sync.aligned.m8n8.x4.shared.b16 {%0,%1,%2,%3}, [%4];"
        : "=r"(r[0]), "=r"(r[1]), "=r"(r[2]), "=r"(r[3]) : "r"(a));
}
__device__ __forceinline__ void ldmx4t(uint32_t* r, uint32_t a) {
    asm volatile("ldmatrix.sync.aligned.m8n8.x4.trans.shared.b16 {%0,%1,%2,%3}, [%4];"
        : "=r"(r[0]), "=r"(r[1]), "=r"(r[2]), "=r"(r[3]) : "r"(a));
}
__device__ __forceinline__ void mma16816(float* c, const uint32_t* a, const uint32_t* b) {
    asm volatile("mma.sync.aligned.m16n8k16.row.col.f32.bf16.bf16.f32 "
        "{%0,%1,%2,%3},{%4,%5,%6,%7},{%8,%9},{%0,%1,%2,%3};"
        : "+f"(c[0]), "+f"(c[1]), "+f"(c[2]), "+f"(c[3])
        : "r"(a[0]), "r"(a[1]), "r"(a[2]), "r"(a[3]), "r"(b[0]), "r"(b[1]));
}

// ---------------- rmsnorm: bf16 hnorm + rrms + fused shared gate ----------------
__global__ void k_rmsnorm(const float* __restrict__ h, const float* __restrict__ w,
                          const float* __restrict__ gw)
{
    int n = blockIdx.x;
    const float4* hp = (const float4*)(h + (size_t)n * D_);
    const float4* wp = (const float4*)w;
    const float4* gp = (const float4*)gw;
    float ss = 0.f, gg = 0.f;
    for (int i = threadIdx.x; i < D_/4; i += 256) {
        float4 v = hp[i], wv = wp[i], gv = gp[i];
        ss += v.x*v.x + v.y*v.y + v.z*v.z + v.w*v.w;
        gg += v.x*wv.x*gv.x + v.y*wv.y*gv.y + v.z*wv.z*gv.z + v.w*wv.w*gv.w;
    }
    __shared__ float red[256], red2[256];
    red[threadIdx.x] = ss; red2[threadIdx.x] = gg; __syncthreads();
    for (int s = 128; s; s >>= 1) {
        if (threadIdx.x < s) { red[threadIdx.x] += red[threadIdx.x + s];
                               red2[threadIdx.x] += red2[threadIdx.x + s]; }
        __syncthreads();
    }
    float rs = rsqrtf(red[0] * (1.f / D_) + 1e-6f);
    if (threadIdx.x == 0) {
        g_gate[n] = 1.f / (1.f + expf(-rs * red2[0]));
        g_rrms[n] = rs;
    }
    __nv_bfloat162* bp = (__nv_bfloat162*)(g_hnorm_bf + (size_t)n * D_);
    for (int i = threadIdx.x; i < D_/4; i += 256) {
        float4 v = hp[i], wv = wp[i];
        v.x *= rs*wv.x; v.y *= rs*wv.y; v.z *= rs*wv.z; v.w *= rs*wv.w;
        bp[i*2+0] = __floats2bfloat162_rn(v.x, v.y);
        bp[i*2+1] = __floats2bfloat162_rn(v.z, v.w);
    }
}

// ---------------- router: recomputes hnorm = h*(rrms*w) in fp32 (bit-identical) ----------------
__global__ void k_router(const float* __restrict__ h, const float* __restrict__ rw,
                         const float* __restrict__ rb, const float* __restrict__ nw)
{
    __shared__ float hs[32][64];
    __shared__ float ws[64][32];
    __shared__ float s_r[32];
    int n0 = blockIdx.x * 32;
    int tid = threadIdx.x;
    int e = tid & 31, tr = tid >> 5;
    if (tid < 32) s_r[tid] = g_rrms[n0 + tid];
    __syncthreads();
    float acc[4] = {0.f,0.f,0.f,0.f};
    for (int k0 = 0; k0 < D_; k0 += 64) {
        #pragma unroll
        for (int i = 0; i < 8; i++) {
            int lin = tid + i*256;
            int t = lin >> 6, k = lin & 63;
            hs[t][k] = h[(size_t)(n0 + t)*D_ + k0 + k] * (s_r[t] * nw[k0 + k]);
            int kw = lin >> 5, ew = lin & 31;
            ws[kw][ew] = rw[(size_t)(k0 + kw)*NEXP + ew];
        }
        __syncthreads();
        #pragma unroll
        for (int kk = 0; kk < 64; kk++)
            #pragma unroll
            for (int i = 0; i < 4; i++)
                acc[i] += hs[tr + 8*i][kk] * ws[kk][e];
        __syncthreads();
    }
    float bias = rb[e];
    #pragma unroll
    for (int i = 0; i < 4; i++) {
        float v = acc[i] + bias;
        g_scores[(n0 + tr + 8*i)*NEXP + e] = 1.f / (1.f + expf(-v));
    }
}

__global__ void k_topk()
{
    int warp = threadIdx.x >> 5, lane = threadIdx.x & 31;
    int n = blockIdx.x * 8 + warp;
    float s = g_scores[n*NEXP + lane];
    float topv[4]; int topi[4];
    #pragma unroll
    for (int k = 0; k < 4; k++) {
        float v = s; int bi = lane;
        #pragma unroll
        for (int off = 16; off; off >>= 1) {
            float v2 = __shfl_xor_sync(0xffffffffu, v, off);
            int   i2 = __shfl_xor_sync(0xffffffffu, bi, off);
            if (v2 > v || (v2 == v && i2 < bi)) { v = v2; bi = i2; }
        }
        topv[k] = v; topi[k] = bi;
        if (lane == bi) s = -1e30f;
    }
    if (lane == 0) {
        float inv = 1.f / (topv[0]+topv[1]+topv[2]+topv[3] + 1e-8f);
        #pragma unroll
        for (int k = 0; k < 4; k++) {
            g_topw[n*4 + k] = topv[k] * inv;
            g_topi[n*4 + k] = topi[k];
            atomicAdd(&g_count[topi[k]], 1);
        }
    }
}

__global__ void k_colsum()
{
    int e = blockIdx.x;
    float s = 0.f;
    for (int n = threadIdx.x; n < NTOK; n += 256) s += g_scores[n*NEXP + e];
    __shared__ float red[256];
    red[threadIdx.x] = s; __syncthreads();
    for (int st = 128; st; st >>= 1) {
        if (threadIdx.x < st) red[threadIdx.x] += red[threadIdx.x + st];
        __syncthreads();
    }
    if (threadIdx.x == 0) g_Psum[e] = red[0];
}

__global__ void k_offsets()
{
    if (threadIdx.x == 0) {
        int acc = 0, nt = 0;
        for (int e = 0; e < NEXP; e++) {
            g_off[e] = acc; g_cursor[e] = acc;
            int nep = (g_count[e] + 127) & ~127;
            for (int r = 0; r < nep; r += 128) {
                g_tile_e[nt] = e; g_tile_r[nt] = acc + r; nt++;
            }
            acc += nep;
        }
        g_off[NEXP] = acc;
        g_ntiles = nt;
    }
}

__global__ void k_assign()
{
    int n = blockIdx.x * 256 + threadIdx.x;
    if (n >= NTOK) return;
    #pragma unroll
    for (int k = 0; k < 4; k++) {
        int e = g_topi[n*4 + k];
        int pos = atomicAdd(&g_cursor[e], 1);
        g_assign_tok[pos] = n;
        g_assign_pos[n*4 + k] = pos;
    }
}

// ---------------- combine: 4 tokens/block, 64 threads/token, 4 cols/thread ----------------
__global__ void k_combine()
{
    int tid = threadIdx.x;
    int n = blockIdx.x * 4 + (tid >> 6);
    int c = (tid & 63) * 4;
    float a0 = 0.f, a1 = 0.f, a2 = 0.f, a3 = 0.f;
    #pragma unroll
    for (int k = 0; k < 4; k++) {
        int pos = g_assign_pos[n*4 + k];
        float w = g_topw[n*4 + k];
        uint2 v = *(const uint2*)(g_contrib_bf + (size_t)pos * LAT + c);
        __nv_bfloat162 p0 = *(__nv_bfloat162*)&v.x;
        __nv_bfloat162 p1 = *(__nv_bfloat162*)&v.y;
        a0 += w * __low2float(p0);  a1 += w * __high2float(p0);
        a2 += w * __low2float(p1);  a3 += w * __high2float(p1);
    }
    __nv_bfloat162 o0 = __floats2bfloat162_rn(a0, a1);
    __nv_bfloat162 o1 = __floats2bfloat162_rn(a2, a3);
    uint2 ov = { *(uint32_t*)&o0, *(uint32_t*)&o1 };
    *(uint2*)(g_cat + (size_t)n * KCAT + c) = ov;
}

__global__ void k_lb(float* out, int out_size)
{
    if (threadIdx.x == 0 && out_size > NTOK * D_) {
        float s = 0.f;
        for (int e = 0; e < NEXP; e++)
            s += ((float)g_count[e] / NTOK) * (g_Psum[e] / NTOK);
        out[NTOK * D_] = (float)NEXP * s * 1e-4f;
    }
}

// ---------------- merged fp32->bf16 conversion (7 segments, one launch) ----------------
#define NSEG 7
struct CvtTable {
    const float* src[NSEG];
    __nv_bfloat16* dst[NSEG];
    int start[NSEG + 1];   // prefix sums of blocks (each block = 4096 elts)
};
__global__ void k_cvt_all(CvtTable t)
{
    int b = blockIdx.x;
    int s = 0;
    #pragma unroll
    for (int i = 1; i < NSEG; i++) if (b >= t.start[i]) s = i;
    long off = ((long)(b - t.start[s]) * 256 + threadIdx.x) * 16;
    const float* a = t.src[s] + off;
    __nv_bfloat16* o = t.dst[s] + off;
    float4 v0 = *(const float4*)(a);
    float4 v1 = *(const float4*)(a + 4);
    float4 v2 = *(const float4*)(a + 8);
    float4 v3 = *(const float4*)(a + 12);
    __nv_bfloat162 p[8];
    p[0] = __floats2bfloat162_rn(v0.x, v0.y);
    p[1] = __floats2bfloat162_rn(v0.z, v0.w);
    p[2] = __floats2bfloat162_rn(v1.x, v1.y);
    p[3] = __floats2bfloat162_rn(v1.z, v1.w);
    p[4] = __floats2bfloat162_rn(v2.x, v2.y);
    p[5] = __floats2bfloat162_rn(v2.z, v2.w);
    p[6] = __floats2bfloat162_rn(v3.x, v3.y);
    p[7] = __floats2bfloat162_rn(v3.z, v3.w);
    *(uint4*)(o)     = *(uint4*)&p[0];
    *(uint4*)(o + 8) = *(uint4*)&p[4];
}

// ====== DUAL mma GEMM (gate+lin, fused spike): 128 thr, 2x2 warps, 64x32 dual,
//        BN=64 per set, BK=64, 2-stage. 2 CTAs/SM. ======
template<bool GROUPED, bool GATHER, bool GATED>
__global__ void __launch_bounds__(128)
k_mmdual(const __nv_bfloat16* __restrict__ A, int lda,
         const __nv_bfloat16* __restrict__ Bt, long bstride, int ldb,
         __nv_bfloat16* __restrict__ Cout, int ldc,
         const float* __restrict__ vth, int HID, int K)
{
    extern __shared__ __align__(16) char smem[];
    __shared__ int s_tok[BM];

    const int tid = threadIdx.x;
    const int lane = tid & 31;
    const int wid = tid >> 5;
    const int wm = wid >> 1, wn = wid & 1;

    int e = 0, r0, n0;
    if (GROUPED) {
        int bt = blockIdx.x;
        if (bt >= g_ntiles) return;
        e = g_tile_e[bt]; r0 = g_tile_r[bt]; n0 = blockIdx.y * BND;
    } else {
        r0 = blockIdx.y * BM; n0 = blockIdx.x * BND;
    }
    const __nv_bfloat16* B = Bt + (GROUPED ? (size_t)e * bstride : 0);

    const uint32_t sb = s2u(smem);
    const uint32_t LDA_B = (BK + 8) * 2;    // 144
    const uint32_t LDB_B = (BND + 8) * 2;   // 144
    const uint32_t A_ST = BM * LDA_B;       // 18432
    const uint32_t B_ST = BK * LDB_B;       // 9216
    const uint32_t bOff  = DSTG * A_ST;
    const uint32_t b2Off = DSTG * (A_ST + B_ST);

    if (GATHER) {
        s_tok[tid] = g_assign_tok[r0 + tid];
        __syncthreads();
    }

    const int nk = K / BK;

    auto issue = [&](int kt) {
        int st = kt & 1;
        uint32_t sa  = sb + st * A_ST;
        uint32_t sbb = sb + bOff + st * B_ST;
        uint32_t sb2 = sb + b2Off + st * B_ST;
        #pragma unroll
        for (int i = 0; i < 8; i++) {
            int lin = i*128 + tid;
            int row = lin >> 3, c8 = (lin & 7) * 8;
            const __nv_bfloat16* src = GATHER
                ? A + (size_t)s_tok[row]*lda + kt*BK + c8
                : A + (size_t)(r0 + row)*lda + kt*BK + c8;
            cp16(sa + row*LDA_B + c8*2, src);
        }
        #pragma unroll
        for (int i = 0; i < 4; i++) {
            int lin = i*128 + tid;
            int row = lin >> 3, c8 = (lin & 7) * 8;
            cp16(sbb + row*LDB_B + c8*2, B + (size_t)(kt*BK + row)*ldb + n0 + c8);
            cp16(sb2 + row*LDB_B + c8*2, B + (size_t)(kt*BK + row)*ldb + (n0 + HID) + c8);
        }
        asm volatile("cp.async.commit_group;" ::: "memory");
    };

    float acc [4][4][4], acc2[4][4][4];
    #pragma unroll
    for (int i = 0; i < 4; i++)
        #pragma unroll
        for (int j = 0; j < 4; j++)
            #pragma unroll
            for (int t = 0; t < 4; t++) { acc[i][j][t] = 0.f; acc2[i][j][t] = 0.f; }

    issue(0);

    for (int kt = 0; kt < nk; kt++) {
        asm volatile("cp.async.wait_group 0;" ::: "memory");
        __syncthreads();
        if (kt + 1 < nk) issue(kt + 1);

        int st = kt & 1;
        uint32_t sa  = sb + st * A_ST;
        uint32_t sbb = sb + bOff + st * B_ST;
        uint32_t sb2 = sb + b2Off + st * B_ST;

        #pragma unroll
        for (int k16 = 0; k16 < BK/16; k16++) {
            uint32_t a[4][4];
            #pragma unroll
            for (int mi = 0; mi < 4; mi++) {
                uint32_t addr = sa + (wm*64 + mi*16 + (lane & 15))*LDA_B
                                   + (k16*16 + (lane >> 4)*8)*2;
                ldmx4(a[mi], addr);
            }
            uint32_t b[4][2], b2[4][2];
            #pragma unroll
            for (int nj = 0; nj < 2; nj++) {
                uint32_t addr = sbb + (k16*16 + (lane & 15))*LDB_B
                                    + (wn*32 + nj*16 + (lane >> 4)*8)*2;
                uint32_t r[4]; ldmx4t(r, addr);
                b[nj*2][0] = r[0]; b[nj*2][1] = r[1];
                b[nj*2+1][0] = r[2]; b[nj*2+1][1] = r[3];
                uint32_t addr2 = sb2 + (k16*16 + (lane & 15))*LDB_B
                                     + (wn*32 + nj*16 + (lane >> 4)*8)*2;
                uint32_t r2[4]; ldmx4t(r2, addr2);
                b2[nj*2][0] = r2[0]; b2[nj*2][1] = r2[1];
                b2[nj*2+1][0] = r2[2]; b2[nj*2+1][1] = r2[3];
            }
            #pragma unroll
            for (int mi = 0; mi < 4; mi++)
                #pragma unroll
                for (int n8 = 0; n8 < 4; n8++) {
                    mma16816(acc[mi][n8], a[mi], b[n8]);
                    mma16816(acc2[mi][n8], a[mi], b2[n8]);
                }
        }
    }

    const int rbase = r0 + wm*64;
    const int cbase = wn*32;
    const float* vthE = vth + (GROUPED ? (size_t)e * HID : 0);
    #pragma unroll
    for (int mi = 0; mi < 4; mi++) {
        int r = rbase + mi*16 + (lane >> 2);
        float gs0 = GATED ? g_gate[r]     : 1.f;
        float gs1 = GATED ? g_gate[r + 8] : 1.f;
        #pragma unroll
        for (int n8 = 0; n8 < 4; n8++) {
            int c = n0 + cbase + n8*8 + (lane & 3)*2;
            float v0 = vthE[c], v1 = vthE[c + 1];
            float o0 = (acc[mi][n8][0] >= v0 ? v0 : 0.f) * acc2[mi][n8][0] * gs0;
            float o1 = (acc[mi][n8][1] >= v1 ? v1 : 0.f) * acc2[mi][n8][1] * gs0;
            float o2 = (acc[mi][n8][2] >= v0 ? v0 : 0.f) * acc2[mi][n8][2] * gs1;
            float o3 = (acc[mi][n8][3] >= v1 ? v1 : 0.f) * acc2[mi][n8][3] * gs1;
            *(__nv_bfloat162*)(Cout + (size_t)r*ldc + c)     = __floats2bfloat162_rn(o0, o1);
            *(__nv_bfloat162*)(Cout + (size_t)(r+8)*ldc + c) = __floats2bfloat162_rn(o2, o3);
        }
    }
}

// ====== non-dual mma GEMM: 128 thr, 4 warps (2x2), warp 64x64, BK=64, 3-stage ======
template<bool GROUPED, bool RESID, bool OUTBF>
__global__ void __launch_bounds__(128)
k_mm64(const __nv_bfloat16* __restrict__ A, int lda,
       const __nv_bfloat16* __restrict__ Bt, long bstride, int ldb,
       void* __restrict__ Cout, int ldc,
       const float* __restrict__ resid, int ldr, int K)
{
    extern __shared__ __align__(16) char smem[];

    const int tid = threadIdx.x;
    const int lane = tid & 31;
    const int wid = tid >> 5;
    const int wm = wid >> 1, wn = wid & 1;

    int e = 0, r0, n0;
    if (GROUPED) {
        int bt = blockIdx.x;
        if (bt >= g_ntiles) return;
        e = g_tile_e[bt]; r0 = g_tile_r[bt]; n0 = blockIdx.y * BN;
    } else {
        r0 = blockIdx.y * BM; n0 = blockIdx.x * BN;
    }
    const __nv_bfloat16* B = Bt + (GROUPED ? (size_t)e * bstride : 0);

    const uint32_t sb = s2u(smem);
    const uint32_t LDA_B = (BK + 8) * 2;
    const uint32_t LDB_B = (BN + 8) * 2;
    const uint32_t A_ST = BM * LDA_B;
    const uint32_t B_ST = BK * LDB_B;
    const uint32_t bOff = STG * A_ST;

    const int nk = K / BK;

    auto issue = [&](int kt) {
        int st = kt % STG;
        uint32_t sa  = sb + st * A_ST;
        uint32_t sbb = sb + bOff + st * B_ST;
        #pragma unroll
        for (int i = 0; i < 8; i++) {
            int lin = i*128 + tid;
            int row = lin >> 3, c8 = (lin & 7) * 8;
            cp16(sa + row*LDA_B + c8*2, A + (size_t)(r0 + row)*lda + kt*BK + c8);
        }
        #pragma unroll
        for (int i = 0; i < 8; i++) {
            int lin = i*128 + tid;
            int row = lin >> 4, c8 = (lin & 15) * 8;
            cp16(sbb + row*LDB_B + c8*2, B + (size_t)(kt*BK + row)*ldb + n0 + c8);
        }
        asm volatile("cp.async.commit_group;" ::: "memory");
    };

    float acc[4][8][4];
    #pragma unroll
    for (int i = 0; i < 4; i++)
        #pragma unroll
        for (int j = 0; j < 8; j++)
            #pragma unroll
            for (int t = 0; t < 4; t++) acc[i][j][t] = 0.f;

    issue(0);
    if (nk > 1) issue(1);

    for (int kt = 0; kt < nk; kt++) {
        if (kt + 2 < nk) asm volatile("cp.async.wait_group 1;" ::: "memory");
        else             asm volatile("cp.async.wait_group 0;" ::: "memory");
        __syncthreads();
        if (kt + 2 < nk) issue(kt + 2);

        int st = kt % STG;
        uint32_t sa  = sb + st * A_ST;
        uint32_t sbb = sb + bOff + st * B_ST;

        #pragma unroll
        for (int k16 = 0; k16 < BK/16; k16++) {
            uint32_t a[4][4];
            #pragma unroll
            for (int mi = 0; mi < 4; mi++) {
                uint32_t addr = sa + (wm*64 + mi*16 + (lane & 15))*LDA_B
                                   + (k16*16 + (lane >> 4)*8)*2;
                ldmx4(a[mi], addr);
            }
            uint32_t b[8][2];
            #pragma unroll
            for (int nj = 0; nj < 4; nj++) {
                uint32_t addr = sbb + (k16*16 + (lane & 15))*LDB_B
                                    + (wn*64 + nj*16 + (lane >> 4)*8)*2;
                uint32_t r[4]; ldmx4t(r, addr);
                b[nj*2][0] = r[0]; b[nj*2][1] = r[1];
                b[nj*2+1][0] = r[2]; b[nj*2+1][1] = r[3];
            }
            #pragma unroll
            for (int mi = 0; mi < 4; mi++)
                #pragma unroll
                for (int n8 = 0; n8 < 8; n8++)
                    mma16816(acc[mi][n8], a[mi], b[n8]);
        }
    }

    const int rbase = r0 + wm*64;
    const int cbase = wn*64;
    #pragma unroll
    for (int mi = 0; mi < 4; mi++) {
        int r = rbase + mi*16 + (lane >> 2);
        #pragma unroll
        for (int n8 = 0; n8 < 8; n8++) {
            int c = n0 + cbase + n8*8 + (lane & 3)*2;
            float o0 = acc[mi][n8][0], o1 = acc[mi][n8][1];
            float o2 = acc[mi][n8][2], o3 = acc[mi][n8][3];
            if (RESID) {
                float2 r0v = *(const float2*)(resid + (size_t)r*ldr + c);
                float2 r1v = *(const float2*)(resid + (size_t)(r+8)*ldr + c);
                o0 += r0v.x; o1 += r0v.y; o2 += r1v.x; o3 += r1v.y;
            }
            if (OUTBF) {
                __nv_bfloat16* op = (__nv_bfloat16*)Cout;
                *(__nv_bfloat162*)(op + (size_t)r*ldc + c)     = __floats2bfloat162_rn(o0, o1);
                *(__nv_bfloat162*)(op + (size_t)(r+8)*ldc + c) = __floats2bfloat162_rn(o2, o3);
            } else {
                float* op = (float*)Cout;
                *(float2*)(op + (size_t)r*ldc + c)     = make_float2(o0, o1);
                *(float2*)(op + (size_t)(r+8)*ldc + c) = make_float2(o2, o3);
            }
        }
    }
}

// ---------------- launch ----------------
extern "C" void kernel_launch(void* const* d_in, const int* in_sizes, int n_in,
                              void* d_out, int out_size)
{
    const float* h         = (const float*)d_in[0];
    const float* norm_w    = (const float*)d_in[1];
    const float* latent_dw = (const float*)d_in[2];
    const float* latent_uw = (const float*)d_in[3];
    const float* router_w  = (const float*)d_in[4];
    const float* router_b  = (const float*)d_in[5];
    const float* ew1       = (const float*)d_in[6];
    const float* evth      = (const float*)d_in[7];
    const float* ew2       = (const float*)d_in[8];
    const float* sw1       = (const float*)d_in[9];
    const float* svth      = (const float*)d_in[10];
    const float* sw2       = (const float*)d_in[11];
    const float* sgw       = (const float*)d_in[12];
    const float* opw       = (const float*)d_in[13];
    float* out = (float*)d_out;

    auto MMe1 = k_mmdual<true , true , false>;  // exp1 fused spike -> ACTb
    auto MMs1 = k_mmdual<false, false, true >;  // shared_w1 fused spike*gate -> g_cat[:,256:]
    auto MMld = k_mm64<false, false, true >;    // latent_down -> latent bf16
    auto MMe2 = k_mm64<true , false, true >;    // exp2 -> contrib bf16
    auto MMwc = k_mm64<false, false, true >;    // W_comb = catW @ opw -> bf16
    auto MMfin= k_mm64<false, true , false>;    // out = h + cat @ W_comb (fp32)

    const uint32_t A_ST  = BM*(BK+8)*2;         // 18432
    const uint32_t B_ST  = BK*(BN+8)*2;         // 17408
    const uint32_t BD_ST = BK*(BND+8)*2;        // 9216
    const int SM1 = STG*(A_ST + B_ST);          // 107520
    const int SM2 = DSTG*(A_ST + 2*BD_ST);      // 73728
    cudaFuncSetAttribute(MMe1, cudaFuncAttributeMaxDynamicSharedMemorySize, SM2);
    cudaFuncSetAttribute(MMs1, cudaFuncAttributeMaxDynamicSharedMemorySize, SM2);
    cudaFuncSetAttribute(MMld, cudaFuncAttributeMaxDynamicSharedMemorySize, SM1);
    cudaFuncSetAttribute(MMe2, cudaFuncAttributeMaxDynamicSharedMemorySize, SM1);
    cudaFuncSetAttribute(MMwc, cudaFuncAttributeMaxDynamicSharedMemorySize, SM1);
    cudaFuncSetAttribute(MMfin,cudaFuncAttributeMaxDynamicSharedMemorySize, SM1);

    void *p_count, *p_atok, *p_hbf, *p_lbf, *p_ACTb, *p_contrib, *p_cat;
    void *p_ldw, *p_catW, *p_Wcomb, *p_ew1, *p_ew2, *p_sw1, *p_opw;
    cudaGetSymbolAddress(&p_count, g_count);
    cudaGetSymbolAddress(&p_atok,  g_assign_tok);
    cudaGetSymbolAddress(&p_hbf,   g_hnorm_bf);
    cudaGetSymbolAddress(&p_lbf,   g_latent_bf);
    cudaGetSymbolAddress(&p_ACTb,  g_ACTb);
    cudaGetSymbolAddress(&p_contrib, g_contrib_bf);
    cudaGetSymbolAddress(&p_cat,   g_cat);
    cudaGetSymbolAddress(&p_ldw,   g_ldw_bf);
    cudaGetSymbolAddress(&p_catW,  g_catW);
    cudaGetSymbolAddress(&p_Wcomb, g_Wcomb);
    cudaGetSymbolAddress(&p_ew1,   g_ew1_bf);
    cudaGetSymbolAddress(&p_ew2,   g_ew2_bf);
    cudaGetSymbolAddress(&p_sw1,   g_sw1_bf);
    cudaGetSymbolAddress(&p_opw,   g_opw_bf);

    // ---- merged weight conversion table (block = 4096 elts; all sizes exact multiples) ----
    CvtTable t;
    t.src[0] = sw1;       t.dst[0] = (__nv_bfloat16*)p_sw1;                         // 2048 blk
    t.src[1] = latent_dw; t.dst[1] = (__nv_bfloat16*)p_ldw;                         // 128
    t.src[2] = latent_uw; t.dst[2] = (__nv_bfloat16*)p_catW;                        // 128
    t.src[3] = ew1;       t.dst[3] = (__nv_bfloat16*)p_ew1;                         // 4096
    t.src[4] = ew2;       t.dst[4] = (__nv_bfloat16*)p_ew2;                         // 2048
    t.src[5] = sw2;       t.dst[5] = (__nv_bfloat16*)p_catW + (size_t)LAT*D_;       // 1024
    t.src[6] = opw;       t.dst[6] = (__nv_bfloat16*)p_opw;                         // 1024
    t.start[0] = 0;    t.start[1] = 2048; t.start[2] = 2176; t.start[3] = 2304;
    t.start[4] = 6400; t.start[5] = 8448; t.start[6] = 9472; t.start[7] = 10496;

    k_rmsnorm<<<NTOK, 256>>>(h, norm_w, sgw);
    k_cvt_all<<<10496, 256>>>(t);

    // big DUAL shared_w1 GEMM
    MMs1<<<dim3(SH/BND, NTOK/128), 128, SM2>>>((const __nv_bfloat16*)p_hbf, D_,
        (const __nv_bfloat16*)p_sw1, 0, 2*SH,
        (__nv_bfloat16*)p_cat + LAT, KCAT, svth, SH, D_);

    // W_comb = [latent_up; shared_w2] @ opw   (2304 x 2048, K=2048) -> bf16
    MMwc<<<dim3(D_/128, KCAT/128), 128, SM1>>>((const __nv_bfloat16*)p_catW, D_,
        (const __nv_bfloat16*)p_opw, 0, D_, p_Wcomb, D_, nullptr, 0, D_);

    cudaMemsetAsync(p_count, 0, NEXP * sizeof(int));
    cudaMemsetAsync(p_atok,  0, ATOTP * sizeof(int));

    k_router <<<NTOK/32, 256>>>(h, router_w, router_b, norm_w);
    k_topk   <<<NTOK/8, 256>>>();
    k_colsum <<<NEXP, 256>>>();
    k_offsets<<<1, 32>>>();
    k_assign <<<NTOK/256, 256>>>();

    // latent = hnorm @ latent_down  -> bf16
    MMld<<<dim3(LAT/128, NTOK/128), 128, SM1>>>((const __nv_bfloat16*)p_hbf, D_,
        (const __nv_bfloat16*)p_ldw, 0, LAT, p_lbf, LAT, nullptr, 0, D_);

    // exp1 fused spike -> ACTb bf16
    MMe1<<<dim3(MAXTILES, EH/BND), 128, SM2>>>((const __nv_bfloat16*)p_lbf, LAT,
        (const __nv_bfloat16*)p_ew1, (long)LAT*2*EH, 2*EH,
        (__nv_bfloat16*)p_ACTb, EH, evth, EH, LAT);

    // exp2 -> contrib bf16
    MMe2<<<dim3(MAXTILES, LAT/128), 128, SM1>>>((const __nv_bfloat16*)p_ACTb, EH,
        (const __nv_bfloat16*)p_ew2, (long)EH*LAT, LAT, p_contrib, LAT, nullptr, 0, EH);

    k_combine<<<NTOK/4, 256>>>();

    // out = h + [eout|ACTS] @ W_comb   (K=2304, fp32 out)
    MMfin<<<dim3(D_/128, NTOK/128), 128, SM1>>>((const __nv_bfloat16*)p_cat, KCAT,
        (const __nv_bfloat16*)p_Wcomb, 0, D_, out, D_, h, D_, KCAT);

    k_lb<<<1, 32>>>(out, out_size);
}

// round 15
// speedup vs baseline: 1.0693x; 1.0007x over previous
#include <cuda_runtime.h>
#include <cuda_bf16.h>
#include <math.h>
#include <stdint.h>

// ---------------- problem constants ----------------
#define D_      2048
#define NTOK    8192
#define LAT     256
#define NEXP    32
#define EH      1024
#define SH      2048
#define ATOT    (NTOK*4)
#define ATOTP   (ATOT + NEXP*128)   // 36864
#define MAXTILES (ATOTP/128)        // 288
#define KCAT    (LAT + SH)          // 2304

#define BM 128
#define BN 128
#define BK 64
#define STG 3          // non-dual stages
#define DSTG 2         // dual stages
#define BND 64         // dual per-set N tile

// ---------------- device scratch ----------------
__device__ __nv_bfloat16 g_hnorm_bf[NTOK*D_];
__device__ float g_rrms  [NTOK];
__device__ float g_scores[NTOK*NEXP];
__device__ __nv_bfloat16 g_latent_bf[NTOK*LAT];
__device__ __nv_bfloat16 g_ACTb[(size_t)ATOTP*EH];
__device__ __nv_bfloat16 g_contrib_bf[(size_t)ATOTP*LAT];
__device__ __nv_bfloat16 g_cat[(size_t)NTOK*KCAT];     // [eout | ACTS]
__device__ float g_gate  [NTOK];
__device__ float g_Psum  [NEXP];
__device__ int   g_count [NEXP];
__device__ int   g_off   [NEXP+1];
__device__ int   g_cursor[NEXP];
__device__ int   g_tile_e[MAXTILES];
__device__ int   g_tile_r[MAXTILES];
__device__ int   g_ntiles;
__device__ int   g_assign_tok[ATOTP];
__device__ int   g_assign_pos[ATOT];
__device__ int   g_topi[ATOT];
__device__ float g_topw[ATOT];

// bf16 weights
__device__ __nv_bfloat16 g_ldw_bf[(size_t)D_*LAT];
__device__ __nv_bfloat16 g_catW  [(size_t)KCAT*D_];    // [latent_up ; shared_w2]
__device__ __nv_bfloat16 g_Wcomb [(size_t)KCAT*D_];    // catW @ opw (bf16)
__device__ __nv_bfloat16 g_ew1_bf[(size_t)NEXP*LAT*2*EH];
__device__ __nv_bfloat16 g_ew2_bf[(size_t)NEXP*EH*LAT];
__device__ __nv_bfloat16 g_sw1_bf[(size_t)D_*2*SH];
__device__ __nv_bfloat16 g_opw_bf[(size_t)D_*D_];

// ---------------- asm helpers ----------------
__device__ __forceinline__ uint32_t s2u(const void* p) {
    uint32_t a;
    asm("{ .reg .u64 t; cvta.to.shared.u64 t, %1; cvt.u32.u64 %0, t; }" : "=r"(a) : "l"(p));
    return a;
}
__device__ __forceinline__ void cp16(uint32_t d, const void* s) {
    asm volatile("cp.async.cg.shared.global [%0], [%1], 16;" :: "r"(d), "l"(s));
}
__device__ __forceinline__ void ldmx4(uint32_t* r, uint32_t a) {
    asm volatile("ldmatrix.sync.aligned.m8n8.x4.shared.b16 {%0,%1,%2,%3}, [%4];"
        : "=r"(r[0]), "=r"(r[1]), "=r"(r[2]), "=r"(r[3]) : "r"(a));
}
__device__ __forceinline__ void ldmx4t(uint32_t* r, uint32_t a) {
    asm volatile("ldmatrix.sync.aligned.m8n8.x4.trans.shared.b16 {%0,%1,%2,%3}, [%4];"
        : "=r"(r[0]), "=r"(r[1]), "=r"(r[2]), "=r"(r[3]) : "r"(a));
}
__device__ __forceinline__ void mma16816(float* c, const uint32_t* a, const uint32_t* b) {
    asm volatile("mma.sync.aligned.m16n8k16.row.col.f32.bf16.bf16.f32 "
        "{%0,%1,%2,%3},{%4,%5,%6,%7},{%8,%9},{%0,%1,%2,%3};"
        : "+f"(c[0]), "+f"(c[1]), "+f"(c[2]), "+f"(c[3])
        : "r"(a[0]), "r"(a[1]), "r"(a[2]), "r"(a[3]), "r"(b[0]), "r"(b[1]));
}

// ---------------- rmsnorm: bf16 hnorm + rrms + fused shared gate ----------------
__global__ void k_rmsnorm(const float* __restrict__ h, const float* __restrict__ w,
                          const float* __restrict__ gw)
{
    int n = blockIdx.x;
    const float4* hp = (const float4*)(h + (size_t)n * D_);
    const float4* wp = (const float4*)w;
    const float4* gp = (const float4*)gw;
    float ss = 0.f, gg = 0.f;
    for (int i = threadIdx.x; i < D_/4; i += 256) {
        float4 v = hp[i], wv = wp[i], gv = gp[i];
        ss += v.x*v.x + v.y*v.y + v.z*v.z + v.w*v.w;
        gg += v.x*wv.x*gv.x + v.y*wv.y*gv.y + v.z*wv.z*gv.z + v.w*wv.w*gv.w;
    }
    __shared__ float red[256], red2[256];
    red[threadIdx.x] = ss; red2[threadIdx.x] = gg; __syncthreads();
    for (int s = 128; s; s >>= 1) {
        if (threadIdx.x < s) { red[threadIdx.x] += red[threadIdx.x + s];
                               red2[threadIdx.x] += red2[threadIdx.x + s]; }
        __syncthreads();
    }
    float rs = rsqrtf(red[0] * (1.f / D_) + 1e-6f);
    if (threadIdx.x == 0) {
        g_gate[n] = 1.f / (1.f + expf(-rs * red2[0]));
        g_rrms[n] = rs;
    }
    __nv_bfloat162* bp = (__nv_bfloat162*)(g_hnorm_bf + (size_t)n * D_);
    for (int i = threadIdx.x; i < D_/4; i += 256) {
        float4 v = hp[i], wv = wp[i];
        v.x *= rs*wv.x; v.y *= rs*wv.y; v.z *= rs*wv.z; v.w *= rs*wv.w;
        bp[i*2+0] = __floats2bfloat162_rn(v.x, v.y);
        bp[i*2+1] = __floats2bfloat162_rn(v.z, v.w);
    }
}

// ---------------- router: recomputes hnorm = h*(rrms*w) in fp32 (bit-identical) ----------------
__global__ void k_router(const float* __restrict__ h, const float* __restrict__ rw,
                         const float* __restrict__ rb, const float* __restrict__ nw)
{
    __shared__ float hs[32][64];
    __shared__ float ws[64][32];
    __shared__ float s_r[32];
    int n0 = blockIdx.x * 32;
    int tid = threadIdx.x;
    int e = tid & 31, tr = tid >> 5;
    if (tid < 32) s_r[tid] = g_rrms[n0 + tid];
    __syncthreads();
    float acc[4] = {0.f,0.f,0.f,0.f};
    for (int k0 = 0; k0 < D_; k0 += 64) {
        #pragma unroll
        for (int i = 0; i < 8; i++) {
            int lin = tid + i*256;
            int t = lin >> 6, k = lin & 63;
            hs[t][k] = h[(size_t)(n0 + t)*D_ + k0 + k] * (s_r[t] * nw[k0 + k]);
            int kw = lin >> 5, ew = lin & 31;
            ws[kw][ew] = rw[(size_t)(k0 + kw)*NEXP + ew];
        }
        __syncthreads();
        #pragma unroll
        for (int kk = 0; kk < 64; kk++)
            #pragma unroll
            for (int i = 0; i < 4; i++)
                acc[i] += hs[tr + 8*i][kk] * ws[kk][e];
        __syncthreads();
    }
    float bias = rb[e];
    #pragma unroll
    for (int i = 0; i < 4; i++) {
        float v = acc[i] + bias;
        g_scores[(n0 + tr + 8*i)*NEXP + e] = 1.f / (1.f + expf(-v));
    }
}

__global__ void k_topk()
{
    int warp = threadIdx.x >> 5, lane = threadIdx.x & 31;
    int n = blockIdx.x * 8 + warp;
    float s = g_scores[n*NEXP + lane];
    float topv[4]; int topi[4];
    #pragma unroll
    for (int k = 0; k < 4; k++) {
        float v = s; int bi = lane;
        #pragma unroll
        for (int off = 16; off; off >>= 1) {
            float v2 = __shfl_xor_sync(0xffffffffu, v, off);
            int   i2 = __shfl_xor_sync(0xffffffffu, bi, off);
            if (v2 > v || (v2 == v && i2 < bi)) { v = v2; bi = i2; }
        }
        topv[k] = v; topi[k] = bi;
        if (lane == bi) s = -1e30f;
    }
    if (lane == 0) {
        float inv = 1.f / (topv[0]+topv[1]+topv[2]+topv[3] + 1e-8f);
        #pragma unroll
        for (int k = 0; k < 4; k++) {
            g_topw[n*4 + k] = topv[k] * inv;
            g_topi[n*4 + k] = topi[k];
            atomicAdd(&g_count[topi[k]], 1);
        }
    }
}

__global__ void k_colsum()
{
    int e = blockIdx.x;
    float s = 0.f;
    for (int n = threadIdx.x; n < NTOK; n += 256) s += g_scores[n*NEXP + e];
    __shared__ float red[256];
    red[threadIdx.x] = s; __syncthreads();
    for (int st = 128; st; st >>= 1) {
        if (threadIdx.x < st) red[threadIdx.x] += red[threadIdx.x + st];
        __syncthreads();
    }
    if (threadIdx.x == 0) g_Psum[e] = red[0];
}

__global__ void k_offsets()
{
    if (threadIdx.x == 0) {
        int acc = 0, nt = 0;
        for (int e = 0; e < NEXP; e++) {
            g_off[e] = acc; g_cursor[e] = acc;
            int nep = (g_count[e] + 127) & ~127;
            for (int r = 0; r < nep; r += 128) {
                g_tile_e[nt] = e; g_tile_r[nt] = acc + r; nt++;
            }
            acc += nep;
        }
        g_off[NEXP] = acc;
        g_ntiles = nt;
    }
}

__global__ void k_assign()
{
    int n = blockIdx.x * 256 + threadIdx.x;
    if (n >= NTOK) return;
    #pragma unroll
    for (int k = 0; k < 4; k++) {
        int e = g_topi[n*4 + k];
        int pos = atomicAdd(&g_cursor[e], 1);
        g_assign_tok[pos] = n;
        g_assign_pos[n*4 + k] = pos;
    }
}

// ---------------- combine: 4 tokens/block, 64 threads/token, 4 cols/thread ----------------
__global__ void k_combine()
{
    int tid = threadIdx.x;
    int n = blockIdx.x * 4 + (tid >> 6);
    int c = (tid & 63) * 4;
    float a0 = 0.f, a1 = 0.f, a2 = 0.f, a3 = 0.f;
    #pragma unroll
    for (int k = 0; k < 4; k++) {
        int pos = g_assign_pos[n*4 + k];
        float w = g_topw[n*4 + k];
        uint2 v = *(const uint2*)(g_contrib_bf + (size_t)pos * LAT + c);
        __nv_bfloat162 p0 = *(__nv_bfloat162*)&v.x;
        __nv_bfloat162 p1 = *(__nv_bfloat162*)&v.y;
        a0 += w * __low2float(p0);  a1 += w * __high2float(p0);
        a2 += w * __low2float(p1);  a3 += w * __high2float(p1);
    }
    __nv_bfloat162 o0 = __floats2bfloat162_rn(a0, a1);
    __nv_bfloat162 o1 = __floats2bfloat162_rn(a2, a3);
    uint2 ov = { *(uint32_t*)&o0, *(uint32_t*)&o1 };
    *(uint2*)(g_cat + (size_t)n * KCAT + c) = ov;
}

__global__ void k_lb(float* out, int out_size)
{
    if (threadIdx.x == 0 && out_size > NTOK * D_) {
        float s = 0.f;
        for (int e = 0; e < NEXP; e++)
            s += ((float)g_count[e] / NTOK) * (g_Psum[e] / NTOK);
        out[NTOK * D_] = (float)NEXP * s * 1e-4f;
    }
}

// ---------------- merged fp32->bf16 conversion (7 segments, one launch) ----------------
#define NSEG 7
struct CvtTable {
    const float* src[NSEG];
    __nv_bfloat16* dst[NSEG];
    int start[NSEG + 1];   // prefix sums of blocks (each block = 4096 elts)
};
__global__ void k_cvt_all(CvtTable t)
{
    int b = blockIdx.x;
    int s = 0;
    #pragma unroll
    for (int i = 1; i < NSEG; i++) if (b >= t.start[i]) s = i;
    long off = ((long)(b - t.start[s]) * 256 + threadIdx.x) * 16;
    const float* a = t.src[s] + off;
    __nv_bfloat16* o = t.dst[s] + off;
    float4 v0 = *(const float4*)(a);
    float4 v1 = *(const float4*)(a + 4);
    float4 v2 = *(const float4*)(a + 8);
    float4 v3 = *(const float4*)(a + 12);
    __nv_bfloat162 p[8];
    p[0] = __floats2bfloat162_rn(v0.x, v0.y);
    p[1] = __floats2bfloat162_rn(v0.z, v0.w);
    p[2] = __floats2bfloat162_rn(v1.x, v1.y);
    p[3] = __floats2bfloat162_rn(v1.z, v1.w);
    p[4] = __floats2bfloat162_rn(v2.x, v2.y);
    p[5] = __floats2bfloat162_rn(v2.z, v2.w);
    p[6] = __floats2bfloat162_rn(v3.x, v3.y);
    p[7] = __floats2bfloat162_rn(v3.z, v3.w);
    *(uint4*)(o)     = *(uint4*)&p[0];
    *(uint4*)(o + 8) = *(uint4*)&p[4];
}

// ====== DUAL mma GEMM (gate+lin, fused spike): 128 thr, 2x2 warps, 64x32 dual,
//        BN=64 per set, BK=64, 2-stage. 2 CTAs/SM. ======
template<bool GROUPED, bool GATHER, bool GATED>
__global__ void __launch_bounds__(128)
k_mmdual(const __nv_bfloat16* __restrict__ A, int lda,
         const __nv_bfloat16* __restrict__ Bt, long bstride, int ldb,
         __nv_bfloat16* __restrict__ Cout, int ldc,
         const float* __restrict__ vth, int HID, int K)
{
    extern __shared__ __align__(16) char smem[];
    __shared__ int s_tok[BM];

    const int tid = threadIdx.x;
    const int lane = tid & 31;
    const int wid = tid >> 5;
    const int wm = wid >> 1, wn = wid & 1;

    int e = 0, r0, n0;
    if (GROUPED) {
        int bt = blockIdx.x;
        if (bt >= g_ntiles) return;
        e = g_tile_e[bt]; r0 = g_tile_r[bt]; n0 = blockIdx.y * BND;
    } else {
        r0 = blockIdx.y * BM; n0 = blockIdx.x * BND;
    }
    const __nv_bfloat16* B = Bt + (GROUPED ? (size_t)e * bstride : 0);

    const uint32_t sb = s2u(smem);
    const uint32_t LDA_B = (BK + 8) * 2;    // 144
    const uint32_t LDB_B = (BND + 8) * 2;   // 144
    const uint32_t A_ST = BM * LDA_B;       // 18432
    const uint32_t B_ST = BK * LDB_B;       // 9216
    const uint32_t bOff  = DSTG * A_ST;
    const uint32_t b2Off = DSTG * (A_ST + B_ST);

    if (GATHER) {
        s_tok[tid] = g_assign_tok[r0 + tid];
        __syncthreads();
    }

    const int nk = K / BK;

    auto issue = [&](int kt) {
        int st = kt & 1;
        uint32_t sa  = sb + st * A_ST;
        uint32_t sbb = sb + bOff + st * B_ST;
        uint32_t sb2 = sb + b2Off + st * B_ST;
        #pragma unroll
        for (int i = 0; i < 8; i++) {
            int lin = i*128 + tid;
            int row = lin >> 3, c8 = (lin & 7) * 8;
            const __nv_bfloat16* src = GATHER
                ? A + (size_t)s_tok[row]*lda + kt*BK + c8
                : A + (size_t)(r0 + row)*lda + kt*BK + c8;
            cp16(sa + row*LDA_B + c8*2, src);
        }
        #pragma unroll
        for (int i = 0; i < 4; i++) {
            int lin = i*128 + tid;
            int row = lin >> 3, c8 = (lin & 7) * 8;
            cp16(sbb + row*LDB_B + c8*2, B + (size_t)(kt*BK + row)*ldb + n0 + c8);
            cp16(sb2 + row*LDB_B + c8*2, B + (size_t)(kt*BK + row)*ldb + (n0 + HID) + c8);
        }
        asm volatile("cp.async.commit_group;" ::: "memory");
    };

    float acc [4][4][4], acc2[4][4][4];
    #pragma unroll
    for (int i = 0; i < 4; i++)
        #pragma unroll
        for (int j = 0; j < 4; j++)
            #pragma unroll
            for (int t = 0; t < 4; t++) { acc[i][j][t] = 0.f; acc2[i][j][t] = 0.f; }

    issue(0);

    for (int kt = 0; kt < nk; kt++) {
        asm volatile("cp.async.wait_group 0;" ::: "memory");
        __syncthreads();
        if (kt + 1 < nk) issue(kt + 1);

        int st = kt & 1;
        uint32_t sa  = sb + st * A_ST;
        uint32_t sbb = sb + bOff + st * B_ST;
        uint32_t sb2 = sb + b2Off + st * B_ST;

        #pragma unroll
        for (int k16 = 0; k16 < BK/16; k16++) {
            uint32_t a[4][4];
            #pragma unroll
            for (int mi = 0; mi < 4; mi++) {
                uint32_t addr = sa + (wm*64 + mi*16 + (lane & 15))*LDA_B
                                   + (k16*16 + (lane >> 4)*8)*2;
                ldmx4(a[mi], addr);
            }
            uint32_t b[4][2], b2[4][2];
            #pragma unroll
            for (int nj = 0; nj < 2; nj++) {
                uint32_t addr = sbb + (k16*16 + (lane & 15))*LDB_B
                                    + (wn*32 + nj*16 + (lane >> 4)*8)*2;
                uint32_t r[4]; ldmx4t(r, addr);
                b[nj*2][0] = r[0]; b[nj*2][1] = r[1];
                b[nj*2+1][0] = r[2]; b[nj*2+1][1] = r[3];
                uint32_t addr2 = sb2 + (k16*16 + (lane & 15))*LDB_B
                                     + (wn*32 + nj*16 + (lane >> 4)*8)*2;
                uint32_t r2[4]; ldmx4t(r2, addr2);
                b2[nj*2][0] = r2[0]; b2[nj*2][1] = r2[1];
                b2[nj*2+1][0] = r2[2]; b2[nj*2+1][1] = r2[3];
            }
            #pragma unroll
            for (int mi = 0; mi < 4; mi++)
                #pragma unroll
                for (int n8 = 0; n8 < 4; n8++) {
                    mma16816(acc[mi][n8], a[mi], b[n8]);
                    mma16816(acc2[mi][n8], a[mi], b2[n8]);
                }
        }
    }

    const int rbase = r0 + wm*64;
    const int cbase = wn*32;
    const float* vthE = vth + (GROUPED ? (size_t)e * HID : 0);
    #pragma unroll
    for (int mi = 0; mi < 4; mi++) {
        int r = rbase + mi*16 + (lane >> 2);
        float gs0 = GATED ? g_gate[r]     : 1.f;
        float gs1 = GATED ? g_gate[r + 8] : 1.f;
        #pragma unroll
        for (int n8 = 0; n8 < 4; n8++) {
            int c = n0 + cbase + n8*8 + (lane & 3)*2;
            float v0 = vthE[c], v1 = vthE[c + 1];
            float o0 = (acc[mi][n8][0] >= v0 ? v0 : 0.f) * acc2[mi][n8][0] * gs0;
            float o1 = (acc[mi][n8][1] >= v1 ? v1 : 0.f) * acc2[mi][n8][1] * gs0;
            float o2 = (acc[mi][n8][2] >= v0 ? v0 : 0.f) * acc2[mi][n8][2] * gs1;
            float o3 = (acc[mi][n8][3] >= v1 ? v1 : 0.f) * acc2[mi][n8][3] * gs1;
            *(__nv_bfloat162*)(Cout + (size_t)r*ldc + c)     = __floats2bfloat162_rn(o0, o1);
            *(__nv_bfloat162*)(Cout + (size_t)(r+8)*ldc + c) = __floats2bfloat162_rn(o2, o3);
        }
    }
}

// ====== non-dual mma GEMM: 128 thr, 4 warps (2x2), warp 64x64, BK=64, 3-stage ======
template<bool GROUPED, bool RESID, bool OUTBF>
__global__ void __launch_bounds__(128)
k_mm64(const __nv_bfloat16* __restrict__ A, int lda,
       const __nv_bfloat16* __restrict__ Bt, long bstride, int ldb,
       void* __restrict__ Cout, int ldc,
       const float* __restrict__ resid, int ldr, int K)
{
    extern __shared__ __align__(16) char smem[];

    const int tid = threadIdx.x;
    const int lane = tid & 31;
    const int wid = tid >> 5;
    const int wm = wid >> 1, wn = wid & 1;

    int e = 0, r0, n0;
    if (GROUPED) {
        int bt = blockIdx.x;
        if (bt >= g_ntiles) return;
        e = g_tile_e[bt]; r0 = g_tile_r[bt]; n0 = blockIdx.y * BN;
    } else {
        r0 = blockIdx.y * BM; n0 = blockIdx.x * BN;
    }
    const __nv_bfloat16* B = Bt + (GROUPED ? (size_t)e * bstride : 0);

    const uint32_t sb = s2u(smem);
    const uint32_t LDA_B = (BK + 8) * 2;
    const uint32_t LDB_B = (BN + 8) * 2;
    const uint32_t A_ST = BM * LDA_B;
    const uint32_t B_ST = BK * LDB_B;
    const uint32_t bOff = STG * A_ST;

    const int nk = K / BK;

    auto issue = [&](int kt) {
        int st = kt % STG;
        uint32_t sa  = sb + st * A_ST;
        uint32_t sbb = sb + bOff + st * B_ST;
        #pragma unroll
        for (int i = 0; i < 8; i++) {
            int lin = i*128 + tid;
            int row = lin >> 3, c8 = (lin & 7) * 8;
            cp16(sa + row*LDA_B + c8*2, A + (size_t)(r0 + row)*lda + kt*BK + c8);
        }
        #pragma unroll
        for (int i = 0; i < 8; i++) {
            int lin = i*128 + tid;
            int row = lin >> 4, c8 = (lin & 15) * 8;
            cp16(sbb + row*LDB_B + c8*2, B + (size_t)(kt*BK + row)*ldb + n0 + c8);
        }
        asm volatile("cp.async.commit_group;" ::: "memory");
    };

    float acc[4][8][4];
    #pragma unroll
    for (int i = 0; i < 4; i++)
        #pragma unroll
        for (int j = 0; j < 8; j++)
            #pragma unroll
            for (int t = 0; t < 4; t++) acc[i][j][t] = 0.f;

    issue(0);
    if (nk > 1) issue(1);

    for (int kt = 0; kt < nk; kt++) {
        if (kt + 2 < nk) asm volatile("cp.async.wait_group 1;" ::: "memory");
        else             asm volatile("cp.async.wait_group 0;" ::: "memory");
        __syncthreads();
        if (kt + 2 < nk) issue(kt + 2);

        int st = kt % STG;
        uint32_t sa  = sb + st * A_ST;
        uint32_t sbb = sb + bOff + st * B_ST;

        #pragma unroll
        for (int k16 = 0; k16 < BK/16; k16++) {
            uint32_t a[4][4];
            #pragma unroll
            for (int mi = 0; mi < 4; mi++) {
                uint32_t addr = sa + (wm*64 + mi*16 + (lane & 15))*LDA_B
                                   + (k16*16 + (lane >> 4)*8)*2;
                ldmx4(a[mi], addr);
            }
            uint32_t b[8][2];
            #pragma unroll
            for (int nj = 0; nj < 4; nj++) {
                uint32_t addr = sbb + (k16*16 + (lane & 15))*LDB_B
                                    + (wn*64 + nj*16 + (lane >> 4)*8)*2;
                uint32_t r[4]; ldmx4t(r, addr);
                b[nj*2][0] = r[0]; b[nj*2][1] = r[1];
                b[nj*2+1][0] = r[2]; b[nj*2+1][1] = r[3];
            }
            #pragma unroll
            for (int mi = 0; mi < 4; mi++)
                #pragma unroll
                for (int n8 = 0; n8 < 8; n8++)
                    mma16816(acc[mi][n8], a[mi], b[n8]);
        }
    }

    const int rbase = r0 + wm*64;
    const int cbase = wn*64;
    #pragma unroll
    for (int mi = 0; mi < 4; mi++) {
        int r = rbase + mi*16 + (lane >> 2);
        #pragma unroll
        for (int n8 = 0; n8 < 8; n8++) {
            int c = n0 + cbase + n8*8 + (lane & 3)*2;
            float o0 = acc[mi][n8][0], o1 = acc[mi][n8][1];
            float o2 = acc[mi][n8][2], o3 = acc[mi][n8][3];
            if (RESID) {
                float2 r0v = *(const float2*)(resid + (size_t)r*ldr + c);
                float2 r1v = *(const float2*)(resid + (size_t)(r+8)*ldr + c);
                o0 += r0v.x; o1 += r0v.y; o2 += r1v.x; o3 += r1v.y;
            }
            if (OUTBF) {
                __nv_bfloat16* op = (__nv_bfloat16*)Cout;
                *(__nv_bfloat162*)(op + (size_t)r*ldc + c)     = __floats2bfloat162_rn(o0, o1);
                *(__nv_bfloat162*)(op + (size_t)(r+8)*ldc + c) = __floats2bfloat162_rn(o2, o3);
            } else {
                float* op = (float*)Cout;
                *(float2*)(op + (size_t)r*ldc + c)     = make_float2(o0, o1);
                *(float2*)(op + (size_t)(r+8)*ldc + c) = make_float2(o2, o3);
            }
        }
    }
}

// ---------------- launch ----------------
extern "C" void kernel_launch(void* const* d_in, const int* in_sizes, int n_in,
                              void* d_out, int out_size)
{
    const float* h         = (const float*)d_in[0];
    const float* norm_w    = (const float*)d_in[1];
    const float* latent_dw = (const float*)d_in[2];
    const float* latent_uw = (const float*)d_in[3];
    const float* router_w  = (const float*)d_in[4];
    const float* router_b  = (const float*)d_in[5];
    const float* ew1       = (const float*)d_in[6];
    const float* evth      = (const float*)d_in[7];
    const float* ew2       = (const float*)d_in[8];
    const float* sw1       = (const float*)d_in[9];
    const float* svth      = (const float*)d_in[10];
    const float* sw2       = (const float*)d_in[11];
    const float* sgw       = (const float*)d_in[12];
    const float* opw       = (const float*)d_in[13];
    float* out = (float*)d_out;

    auto MMe1 = k_mmdual<true , true , false>;  // exp1 fused spike -> ACTb
    auto MMs1 = k_mmdual<false, false, true >;  // shared_w1 fused spike*gate -> g_cat[:,256:]
    auto MMld = k_mm64<false, false, true >;    // latent_down -> latent bf16
    auto MMe2 = k_mm64<true , false, true >;    // exp2 -> contrib bf16
    auto MMwc = k_mm64<false, false, true >;    // W_comb = catW @ opw -> bf16
    auto MMfin= k_mm64<false, true , false>;    // out = h + cat @ W_comb (fp32)

    const uint32_t A_ST  = BM*(BK+8)*2;         // 18432
    const uint32_t B_ST  = BK*(BN+8)*2;         // 17408
    const uint32_t BD_ST = BK*(BND+8)*2;        // 9216
    const int SM1 = STG*(A_ST + B_ST);          // 107520
    const int SM2 = DSTG*(A_ST + 2*BD_ST);      // 73728
    cudaFuncSetAttribute(MMe1, cudaFuncAttributeMaxDynamicSharedMemorySize, SM2);
    cudaFuncSetAttribute(MMs1, cudaFuncAttributeMaxDynamicSharedMemorySize, SM2);
    cudaFuncSetAttribute(MMld, cudaFuncAttributeMaxDynamicSharedMemorySize, SM1);
    cudaFuncSetAttribute(MMe2, cudaFuncAttributeMaxDynamicSharedMemorySize, SM1);
    cudaFuncSetAttribute(MMwc, cudaFuncAttributeMaxDynamicSharedMemorySize, SM1);
    cudaFuncSetAttribute(MMfin,cudaFuncAttributeMaxDynamicSharedMemorySize, SM1);

    void *p_count, *p_atok, *p_hbf, *p_lbf, *p_ACTb, *p_contrib, *p_cat;
    void *p_ldw, *p_catW, *p_Wcomb, *p_ew1, *p_ew2, *p_sw1, *p_opw;
    cudaGetSymbolAddress(&p_count, g_count);
    cudaGetSymbolAddress(&p_atok,  g_assign_tok);
    cudaGetSymbolAddress(&p_hbf,   g_hnorm_bf);
    cudaGetSymbolAddress(&p_lbf,   g_latent_bf);
    cudaGetSymbolAddress(&p_ACTb,  g_ACTb);
    cudaGetSymbolAddress(&p_contrib, g_contrib_bf);
    cudaGetSymbolAddress(&p_cat,   g_cat);
    cudaGetSymbolAddress(&p_ldw,   g_ldw_bf);
    cudaGetSymbolAddress(&p_catW,  g_catW);
    cudaGetSymbolAddress(&p_Wcomb, g_Wcomb);
    cudaGetSymbolAddress(&p_ew1,   g_ew1_bf);
    cudaGetSymbolAddress(&p_ew2,   g_ew2_bf);
    cudaGetSymbolAddress(&p_sw1,   g_sw1_bf);
    cudaGetSymbolAddress(&p_opw,   g_opw_bf);

    // ---- merged weight conversion table (block = 4096 elts; all sizes exact multiples) ----
    CvtTable t;
    t.src[0] = sw1;       t.dst[0] = (__nv_bfloat16*)p_sw1;                         // 2048 blk
    t.src[1] = latent_dw; t.dst[1] = (__nv_bfloat16*)p_ldw;                         // 128
    t.src[2] = latent_uw; t.dst[2] = (__nv_bfloat16*)p_catW;                        // 128
    t.src[3] = ew1;       t.dst[3] = (__nv_bfloat16*)p_ew1;                         // 4096
    t.src[4] = ew2;       t.dst[4] = (__nv_bfloat16*)p_ew2;                         // 2048
    t.src[5] = sw2;       t.dst[5] = (__nv_bfloat16*)p_catW + (size_t)LAT*D_;       // 1024
    t.src[6] = opw;       t.dst[6] = (__nv_bfloat16*)p_opw;                         // 1024
    t.start[0] = 0;    t.start[1] = 2048; t.start[2] = 2176; t.start[3] = 2304;
    t.start[4] = 6400; t.start[5] = 8448; t.start[6] = 9472; t.start[7] = 10496;

    k_rmsnorm<<<NTOK, 256>>>(h, norm_w, sgw);
    k_cvt_all<<<10496, 256>>>(t);

    // big DUAL shared_w1 GEMM
    MMs1<<<dim3(SH/BND, NTOK/128), 128, SM2>>>((const __nv_bfloat16*)p_hbf, D_,
        (const __nv_bfloat16*)p_sw1, 0, 2*SH,
        (__nv_bfloat16*)p_cat + LAT, KCAT, svth, SH, D_);

    // W_comb = [latent_up; shared_w2] @ opw   (2304 x 2048, K=2048) -> bf16
    MMwc<<<dim3(D_/128, KCAT/128), 128, SM1>>>((const __nv_bfloat16*)p_catW, D_,
        (const __nv_bfloat16*)p_opw, 0, D_, p_Wcomb, D_, nullptr, 0, D_);

    cudaMemsetAsync(p_count, 0, NEXP * sizeof(int));
    cudaMemsetAsync(p_atok,  0, ATOTP * sizeof(int));

    k_router <<<NTOK/32, 256>>>(h, router_w, router_b, norm_w);
    k_topk   <<<NTOK/8, 256>>>();
    k_colsum <<<NEXP, 256>>>();
    k_offsets<<<1, 32>>>();
    k_assign <<<NTOK/256, 256>>>();

    // latent = hnorm @ latent_down  -> bf16
    MMld<<<dim3(LAT/128, NTOK/128), 128, SM1>>>((const __nv_bfloat16*)p_hbf, D_,
        (const __nv_bfloat16*)p_ldw, 0, LAT, p_lbf, LAT, nullptr, 0, D_);

    // exp1 fused spike -> ACTb bf16
    MMe1<<<dim3(MAXTILES, EH/BND), 128, SM2>>>((const __nv_bfloat16*)p_lbf, LAT,
        (const __nv_bfloat16*)p_ew1, (long)LAT*2*EH, 2*EH,
        (__nv_bfloat16*)p_ACTb, EH, evth, EH, LAT);

    // exp2 -> contrib bf16
    MMe2<<<dim3(MAXTILES, LAT/128), 128, SM1>>>((const __nv_bfloat16*)p_ACTb, EH,
        (const __nv_bfloat16*)p_ew2, (long)EH*LAT, LAT, p_contrib, LAT, nullptr, 0, EH);

    k_combine<<<NTOK/4, 256>>>();

    // out = h + [eout|ACTS] @ W_comb   (K=2304, fp32 out)
    MMfin<<<dim3(D_/128, NTOK/128), 128, SM1>>>((const __nv_bfloat16*)p_cat, KCAT,
        (const __nv_bfloat16*)p_Wcomb, 0, D_, out, D_, h, D_, KCAT);

    k_lb<<<1, 32>>>(out, out_size);
}